// round 8
// baseline (speedup 1.0000x reference)
#include <cuda_runtime.h>
#include <cuda_pipeline.h>
#include <cstdint>
#include <math.h>

#define BB 2
#define SS 2049
#define EE 512
#define HH 8
#define WINW 1024
#define MROWS (BB * SS)                  // 4098
#define SCALE 0.125f                     // D^-0.5
#define BIASC (-1.9073486328125e-6f)     // -0.5/(512^2)
#define LOG2E 1.4426950408889634f

// Scratch (device globals: no allocation allowed)
__device__ float g_q[MROWS * EE];
__device__ float g_k[MROWS * EE];
__device__ float g_v[MROWS * EE];
__device__ float g_ao[MROWS * EE];
__device__ float g_gq[MROWS];
__device__ float g_gk[MROWS];

// ============================================================================
// helpers
// ============================================================================
__device__ __forceinline__ float tf32r(float x) {
    uint32_t u;
    asm("cvt.rna.tf32.f32 %0, %1;" : "=r"(u) : "f"(x));
    return __uint_as_float(u);
}
__device__ __forceinline__ void split2(float x, float& hi, float& lo) {
    hi = tf32r(x);
    lo = tf32r(x - hi);
}
__device__ __forceinline__ void mma_tf32(float* d, const uint32_t* a, const uint32_t* b) {
    asm volatile(
        "mma.sync.aligned.m16n8k8.row.col.f32.tf32.tf32.f32 "
        "{%0,%1,%2,%3}, {%4,%5,%6,%7}, {%8,%9}, {%0,%1,%2,%3};"
        : "+f"(d[0]), "+f"(d[1]), "+f"(d[2]), "+f"(d[3])
        : "r"(a[0]), "r"(a[1]), "r"(a[2]), "r"(a[3]), "r"(b[0]), "r"(b[1]));
}
__device__ __forceinline__ float rcpf(float x) {
    float r;
    asm("rcp.approx.f32 %0, %1;" : "=f"(r) : "f"(x));
    return r;
}
__device__ __forceinline__ float ex2f(float x) {
    float r;
    asm("ex2.approx.f32 %0, %1;" : "=f"(r) : "f"(x));
    return r;
}

// ---------------------------------------------------------------------------
// 3xTF32 GEMM body, software-pipelined double-buffered.
// R8: mma issued in 3 passes (al*bh, ah*bl, ah*bh) over all 16 tiles so
// consecutive writes to any accumulator are 16 independent mma apart.
// Per-accumulator FP order is unchanged vs R7.
// ---------------------------------------------------------------------------
#define GSTR 136
#define TILEF (16 * GSTR)
#define GEMM_SMEM (8 * TILEF * 4)

__device__ __forceinline__ void gemm_body(
    const float* __restrict__ A, const float* __restrict__ B,
    const float* __restrict__ bias, float* __restrict__ C, int M,
    int row0, int col0, float* sm)
{
    float* Ah = sm;
    float* Al = sm + 2 * TILEF;
    float* Bh = sm + 4 * TILEF;
    float* Bl = sm + 6 * TILEF;

    const int tid = threadIdx.x;
    const int wid = tid >> 5, lane = tid & 31;
    const int g = lane >> 2, tg = lane & 3;
    const int wm = wid >> 1, wn = wid & 1;
    const int wrow = wm * 32, wcol = wn * 64;

    const int a_r0 = tid >> 2, a_c = (tid & 3) * 4;
    const int b_k0 = tid >> 5, b_c = (tid & 31) * 4;

    float acc[2][8][4];
#pragma unroll
    for (int mt = 0; mt < 2; mt++)
#pragma unroll
        for (int nt = 0; nt < 8; nt++)
#pragma unroll
            for (int e = 0; e < 4; e++) acc[mt][nt][e] = 0.f;

    float4 pa[2], pb[2];

#define G_LDG(K0)                                                              \
    {                                                                          \
        _Pragma("unroll")                                                      \
        for (int it = 0; it < 2; it++) {                                       \
            int r = a_r0 + it * 64;                                            \
            pa[it] = make_float4(0.f, 0.f, 0.f, 0.f);                          \
            if (row0 + r < M)                                                  \
                pa[it] = *(const float4*)&A[(size_t)(row0 + r) * 512 + (K0) + a_c]; \
            int kr = b_k0 + it * 8;                                            \
            pb[it] = *(const float4*)&B[(size_t)((K0) + kr) * 512 + col0 + b_c];    \
        }                                                                      \
    }

#define G_STS(Q)                                                               \
    {                                                                          \
        float* ah = Ah + (Q) * TILEF; float* al = Al + (Q) * TILEF;            \
        float* bh = Bh + (Q) * TILEF; float* bl = Bl + (Q) * TILEF;            \
        _Pragma("unroll")                                                      \
        for (int it = 0; it < 2; it++) {                                       \
            int r = a_r0 + it * 64;                                            \
            float h, l;                                                        \
            split2(pa[it].x, h, l); ah[(a_c + 0) * GSTR + r] = h; al[(a_c + 0) * GSTR + r] = l; \
            split2(pa[it].y, h, l); ah[(a_c + 1) * GSTR + r] = h; al[(a_c + 1) * GSTR + r] = l; \
            split2(pa[it].z, h, l); ah[(a_c + 2) * GSTR + r] = h; al[(a_c + 2) * GSTR + r] = l; \
            split2(pa[it].w, h, l); ah[(a_c + 3) * GSTR + r] = h; al[(a_c + 3) * GSTR + r] = l; \
            int kr = b_k0 + it * 8;                                            \
            float4 hv, lv;                                                     \
            split2(pb[it].x, hv.x, lv.x);                                      \
            split2(pb[it].y, hv.y, lv.y);                                      \
            split2(pb[it].z, hv.z, lv.z);                                      \
            split2(pb[it].w, hv.w, lv.w);                                      \
            *(float4*)&bh[kr * GSTR + b_c] = hv;                               \
            *(float4*)&bl[kr * GSTR + b_c] = lv;                               \
        }                                                                      \
    }

    G_LDG(0);
    G_STS(0);
    G_LDG(16);
    __syncthreads();

    int p = 0;
    for (int k0 = 0; k0 < 512; k0 += 16) {
        if (k0 + 16 < 512) {
            G_STS(1 - p);
            if (k0 + 32 < 512) G_LDG(k0 + 32);
        }

        const float* ah_ = Ah + p * TILEF;
        const float* al_ = Al + p * TILEF;
        const float* bh_ = Bh + p * TILEF;
        const float* bl_ = Bl + p * TILEF;
#pragma unroll
        for (int ks = 0; ks < 2; ks++) {
            const int kk = ks * 8;
            uint32_t ah[2][4], al[2][4];
#pragma unroll
            for (int mt = 0; mt < 2; mt++) {
                int r = wrow + mt * 16;
                ah[mt][0] = __float_as_uint(ah_[(kk + tg) * GSTR + r + g]);
                ah[mt][1] = __float_as_uint(ah_[(kk + tg) * GSTR + r + g + 8]);
                ah[mt][2] = __float_as_uint(ah_[(kk + tg + 4) * GSTR + r + g]);
                ah[mt][3] = __float_as_uint(ah_[(kk + tg + 4) * GSTR + r + g + 8]);
                al[mt][0] = __float_as_uint(al_[(kk + tg) * GSTR + r + g]);
                al[mt][1] = __float_as_uint(al_[(kk + tg) * GSTR + r + g + 8]);
                al[mt][2] = __float_as_uint(al_[(kk + tg + 4) * GSTR + r + g]);
                al[mt][3] = __float_as_uint(al_[(kk + tg + 4) * GSTR + r + g + 8]);
            }
            uint32_t bh[8][2], bl[8][2];
#pragma unroll
            for (int nt = 0; nt < 8; nt++) {
                int c = wcol + nt * 8;
                bh[nt][0] = __float_as_uint(bh_[(kk + tg) * GSTR + c + g]);
                bh[nt][1] = __float_as_uint(bh_[(kk + tg + 4) * GSTR + c + g]);
                bl[nt][0] = __float_as_uint(bl_[(kk + tg) * GSTR + c + g]);
                bl[nt][1] = __float_as_uint(bl_[(kk + tg + 4) * GSTR + c + g]);
            }
            // pass 1: al * bh   (16 independent mma)
#pragma unroll
            for (int mt = 0; mt < 2; mt++)
#pragma unroll
                for (int nt = 0; nt < 8; nt++)
                    mma_tf32(acc[mt][nt], al[mt], bh[nt]);
            // pass 2: ah * bl
#pragma unroll
            for (int mt = 0; mt < 2; mt++)
#pragma unroll
                for (int nt = 0; nt < 8; nt++)
                    mma_tf32(acc[mt][nt], ah[mt], bl[nt]);
            // pass 3: ah * bh
#pragma unroll
            for (int mt = 0; mt < 2; mt++)
#pragma unroll
                for (int nt = 0; nt < 8; nt++)
                    mma_tf32(acc[mt][nt], ah[mt], bh[nt]);
        }

        if (k0 + 16 < 512) {
            __syncthreads();
            p ^= 1;
        }
    }

#pragma unroll
    for (int mt = 0; mt < 2; mt++) {
        int r0 = row0 + wrow + mt * 16 + g;
#pragma unroll
        for (int nt = 0; nt < 8; nt++) {
            int c = col0 + wcol + nt * 8 + 2 * tg;
            float b0v = bias[c], b1v = bias[c + 1];
            if (r0 < M) {
                float2 o = make_float2(acc[mt][nt][0] + b0v, acc[mt][nt][1] + b1v);
                *(float2*)&C[(size_t)r0 * 512 + c] = o;
            }
            if (r0 + 8 < M) {
                float2 o = make_float2(acc[mt][nt][2] + b0v, acc[mt][nt][3] + b1v);
                *(float2*)&C[(size_t)(r0 + 8) * 512 + c] = o;
            }
        }
    }
#undef G_LDG
#undef G_STS
}

__global__ __launch_bounds__(256, 1) void qkv_gemm_kernel(
    const float* __restrict__ A,
    const float* __restrict__ Wq, const float* __restrict__ bq,
    const float* __restrict__ Wk, const float* __restrict__ bk,
    const float* __restrict__ Wv, const float* __restrict__ bv,
    float* __restrict__ Cq, float* __restrict__ Ck, float* __restrict__ Cv,
    int M)
{
    extern __shared__ float gsm[];
    const float* B;
    const float* bias;
    float* C;
    if (blockIdx.z == 0)      { B = Wq; bias = bq; C = Cq; }
    else if (blockIdx.z == 1) { B = Wk; bias = bk; C = Ck; }
    else                      { B = Wv; bias = bv; C = Cv; }
    gemm_body(A, B, bias, C, M, blockIdx.y * 128, blockIdx.x * 128, gsm);
}

__global__ __launch_bounds__(256, 1) void gemm_tc_kernel(
    const float* __restrict__ A, const float* __restrict__ B,
    const float* __restrict__ bias, float* __restrict__ C, int M)
{
    extern __shared__ float gsm[];
    gemm_body(A, B, bias, C, M, blockIdx.y * 128, blockIdx.x * 128, gsm);
}

// ---------------------------------------------------------------------------
// Gate dot products
// ---------------------------------------------------------------------------
__global__ __launch_bounds__(128) void gate_kernel(const float* __restrict__ wg)
{
    const int row = blockIdx.x;
    const int tid = threadIdx.x;
    float sq = 0.f, sk = 0.f;
#pragma unroll
    for (int e = tid; e < 512; e += 128) {
        sq += g_q[(size_t)row * 512 + e] * wg[e];
        sk += g_k[(size_t)row * 512 + e] * wg[512 + e];
    }
#pragma unroll
    for (int off = 16; off >= 1; off >>= 1) {
        sq += __shfl_down_sync(0xffffffffu, sq, off);
        sk += __shfl_down_sync(0xffffffffu, sk, off);
    }
    __shared__ float pq[4], pk[4];
    if ((tid & 31) == 0) { pq[tid >> 5] = sq; pk[tid >> 5] = sk; }
    __syncthreads();
    if (tid == 0) {
        g_gq[row] = pq[0] + pq[1] + pq[2] + pq[3];
        g_gk[row] = pk[0] + pk[1] + pk[2] + pk[3];
    }
}

// ---------------------------------------------------------------------------
// TF32 mma.sync flash attention with cp.async double-buffered K/V staging.
// (unchanged from R7)
// ---------------------------------------------------------------------------
#define ASTR 68
#define TILE68 (64 * ASTR)
#define ATTN_SMEM ((6 * TILE68 + 128 + 32) * 4)

__global__ __launch_bounds__(128, 2) void attn_mma_kernel(const float* __restrict__ bg_ptr)
{
    extern __shared__ float sm[];
    float* Qs   = sm;                       // [64][ASTR]
    float* Ps   = sm + 5 * TILE68;          // [64][ASTR]
    float* egk  = sm + 6 * TILE68;          // [2][64]

    const int qb = blockIdx.x, h = blockIdx.y, b = blockIdx.z;
    const int q0 = qb * 64;
    const int tid = threadIdx.x;
    const int lane = tid & 31;
    const int g = lane >> 2, tg = lane & 3;
    const int wrow = (tid >> 5) * 16;
    const float bg = bg_ptr[0];

    const float* qp = g_q + ((size_t)(b * SS)) * EE + h * 64;
    const float* kp = g_k + ((size_t)(b * SS)) * EE + h * 64;
    const float* vp = g_v + ((size_t)(b * SS)) * EE + h * 64;

    int kstart = q0 - WINW; if (kstart < 0) kstart = 0;
    int kend = q0 + 64 + WINW; if (kend > SS) kend = SS;

    const int s_r = tid >> 4, s_c = (tid & 15) * 4;
#define STAGE_KV(K0, BBUF)                                                     \
    {                                                                          \
        float* Kb = sm + (1 + (BBUF)) * TILE68;                                \
        float* Vb = sm + (3 + (BBUF)) * TILE68;                                \
        _Pragma("unroll")                                                      \
        for (int it = 0; it < 8; it++) {                                       \
            int r = s_r + it * 8;                                              \
            int gj = (K0) + r;                                                 \
            size_t off = (size_t)gj * EE + s_c;                                \
            int zf = (gj < SS) ? 0 : 16;                                       \
            __pipeline_memcpy_async(&Kb[r * ASTR + s_c], kp + off, 16, zf);    \
            __pipeline_memcpy_async(&Vb[r * ASTR + s_c], vp + off, 16, zf);    \
        }                                                                      \
        __pipeline_commit();                                                   \
    }

    STAGE_KV(kstart, 0);
    float gk_reg = 0.f;
    if (tid < 64) {
        int gj = kstart + tid;
        gk_reg = (gj < SS) ? g_gk[b * SS + gj] : 0.f;
    }

#pragma unroll
    for (int it = 0; it < 8; it++) {
        int idx = it * 128 + tid;
        int r = idx >> 4, c4 = (idx & 15) * 4;
        int gi = q0 + r;
        float4 v = make_float4(0.f, 0.f, 0.f, 0.f);
        if (gi < SS) v = *(const float4*)(qp + (size_t)gi * EE + c4);
        Qs[r * ASTR + c4 + 0] = tf32r(v.x);
        Qs[r * ASTR + c4 + 1] = tf32r(v.y);
        Qs[r * ASTR + c4 + 2] = tf32r(v.z);
        Qs[r * ASTR + c4 + 3] = tf32r(v.w);
    }
    __syncthreads();

    uint32_t qa[8][4];
#pragma unroll
    for (int kk = 0; kk < 8; kk++) {
        qa[kk][0] = __float_as_uint(Qs[(wrow + g) * ASTR + kk * 8 + tg]);
        qa[kk][1] = __float_as_uint(Qs[(wrow + g + 8) * ASTR + kk * 8 + tg]);
        qa[kk][2] = __float_as_uint(Qs[(wrow + g) * ASTR + kk * 8 + tg + 4]);
        qa[kk][3] = __float_as_uint(Qs[(wrow + g + 8) * ASTR + kk * 8 + tg + 4]);
    }
    const int gi0 = q0 + wrow + g, gi1 = gi0 + 8;
    const float egq0 = __expf(-((gi0 < SS) ? g_gq[b * SS + gi0] : 0.f));
    const float egq1 = __expf(-((gi1 < SS) ? g_gq[b * SS + gi1] : 0.f));

    float oacc[8][4];
#pragma unroll
    for (int nt = 0; nt < 8; nt++)
#pragma unroll
        for (int e = 0; e < 4; e++) oacc[nt][e] = 0.f;
    float l0 = 0.f, l1 = 0.f;

    const float C1 = SCALE * LOG2E;
    const float C2 = BIASC * LOG2E;

    int p = 0;
    for (int k0 = kstart; k0 < kend; k0 += 64, p ^= 1) {
        __pipeline_wait_prior(0);
        __syncthreads();

        if (tid < 64) egk[p * 64 + tid] = __expf(-gk_reg - bg);
        if (k0 + 64 < kend) {
            STAGE_KV(k0 + 64, 1 - p);
            if (tid < 64) {
                int gj = k0 + 64 + tid;
                gk_reg = (gj < SS) ? g_gk[b * SS + gj] : 0.f;
            }
        }
        __syncthreads();

        const float* Kb = sm + (1 + p) * TILE68;
        const float* Vb = sm + (3 + p) * TILE68;
        const float* eg_s = egk + p * 64;

        float sacc[8][4];
#pragma unroll
        for (int nt = 0; nt < 8; nt++)
#pragma unroll
            for (int e = 0; e < 4; e++) sacc[nt][e] = 0.f;
#pragma unroll
        for (int kk = 0; kk < 8; kk++) {
#pragma unroll
            for (int nt = 0; nt < 8; nt++) {
                uint32_t bf[2];
                bf[0] = __float_as_uint(Kb[(nt * 8 + g) * ASTR + kk * 8 + tg]);
                bf[1] = __float_as_uint(Kb[(nt * 8 + g) * ASTR + kk * 8 + tg + 4]);
                mma_tf32(sacc[nt], qa[kk], bf);
            }
        }

        float lt0 = 0.f, lt1 = 0.f;
#pragma unroll
        for (int nt = 0; nt < 8; nt++) {
            int lj = nt * 8 + 2 * tg;
            float2 eg = *(float2*)&eg_s[lj];
            int gj0 = k0 + lj, gj1 = gj0 + 1;

            int d00 = gi0 - gj0, d01 = gi0 - gj1, d10 = gi1 - gj0, d11 = gi1 - gj1;
            float p00, p01, p10, p11;
            {
                float gate = rcpf(fmaf(egq0, eg.x, 1.f));
                float pe = ex2f((sacc[nt][0] * C1 + (float)(d00 * d00) * C2) * gate);
                p00 = (gj0 < SS && d00 <= WINW && d00 >= -WINW) ? tf32r(pe) : 0.f;
            }
            {
                float gate = rcpf(fmaf(egq0, eg.y, 1.f));
                float pe = ex2f((sacc[nt][1] * C1 + (float)(d01 * d01) * C2) * gate);
                p01 = (gj1 < SS && d01 <= WINW && d01 >= -WINW) ? tf32r(pe) : 0.f;
            }
            {
                float gate = rcpf(fmaf(egq1, eg.x, 1.f));
                float pe = ex2f((sacc[nt][2] * C1 + (float)(d10 * d10) * C2) * gate);
                p10 = (gj0 < SS && d10 <= WINW && d10 >= -WINW) ? tf32r(pe) : 0.f;
            }
            {
                float gate = rcpf(fmaf(egq1, eg.y, 1.f));
                float pe = ex2f((sacc[nt][3] * C1 + (float)(d11 * d11) * C2) * gate);
                p11 = (gj1 < SS && d11 <= WINW && d11 >= -WINW) ? tf32r(pe) : 0.f;
            }
            lt0 += p00 + p01;
            lt1 += p10 + p11;
            *(float2*)&Ps[(wrow + g) * ASTR + lj] = make_float2(p00, p01);
            *(float2*)&Ps[(wrow + g + 8) * ASTR + lj] = make_float2(p10, p11);
        }
        lt0 += __shfl_xor_sync(0xffffffffu, lt0, 1);
        lt0 += __shfl_xor_sync(0xffffffffu, lt0, 2);
        lt1 += __shfl_xor_sync(0xffffffffu, lt1, 1);
        lt1 += __shfl_xor_sync(0xffffffffu, lt1, 2);
        l0 += lt0;
        l1 += lt1;
        __syncwarp();

#pragma unroll
        for (int kk = 0; kk < 8; kk++) {
            uint32_t pa[4];
            pa[0] = __float_as_uint(Ps[(wrow + g) * ASTR + kk * 8 + tg]);
            pa[1] = __float_as_uint(Ps[(wrow + g + 8) * ASTR + kk * 8 + tg]);
            pa[2] = __float_as_uint(Ps[(wrow + g) * ASTR + kk * 8 + tg + 4]);
            pa[3] = __float_as_uint(Ps[(wrow + g + 8) * ASTR + kk * 8 + tg + 4]);
#pragma unroll
            for (int nt = 0; nt < 8; nt++) {
                uint32_t bf[2];
                bf[0] = __float_as_uint(Vb[(kk * 8 + tg) * ASTR + nt * 8 + g]);
                bf[1] = __float_as_uint(Vb[(kk * 8 + tg + 4) * ASTR + nt * 8 + g]);
                mma_tf32(oacc[nt], pa, bf);
            }
        }
    }

    const float inv0 = rcpf(l0), inv1 = rcpf(l1);
    float* op = g_ao + ((size_t)(b * SS)) * EE + h * 64;
#pragma unroll
    for (int nt = 0; nt < 8; nt++) {
        int c = nt * 8 + 2 * tg;
        if (gi0 < SS)
            *(float2*)&op[(size_t)gi0 * EE + c] =
                make_float2(oacc[nt][0] * inv0, oacc[nt][1] * inv0);
        if (gi1 < SS)
            *(float2*)&op[(size_t)gi1 * EE + c] =
                make_float2(oacc[nt][2] * inv1, oacc[nt][3] * inv1);
    }
#undef STAGE_KV
}

// ---------------------------------------------------------------------------
extern "C" void kernel_launch(void* const* d_in, const int* in_sizes, int n_in,
                              void* d_out, int out_size)
{
    const float* x  = (const float*)d_in[0];
    const float* Wq = (const float*)d_in[1];
    const float* bq = (const float*)d_in[2];
    const float* Wk = (const float*)d_in[3];
    const float* bk = (const float*)d_in[4];
    const float* Wv = (const float*)d_in[5];
    const float* bv = (const float*)d_in[6];
    const float* Wo = (const float*)d_in[7];
    const float* bo = (const float*)d_in[8];
    const float* wg = (const float*)d_in[9];
    const float* bg = (const float*)d_in[10];
    float* out = (float*)d_out;

    float *pq, *pk, *pv, *pao;
    cudaGetSymbolAddress((void**)&pq, g_q);
    cudaGetSymbolAddress((void**)&pk, g_k);
    cudaGetSymbolAddress((void**)&pv, g_v);
    cudaGetSymbolAddress((void**)&pao, g_ao);

    cudaFuncSetAttribute(attn_mma_kernel,
                         cudaFuncAttributeMaxDynamicSharedMemorySize, ATTN_SMEM);
    cudaFuncSetAttribute(qkv_gemm_kernel,
                         cudaFuncAttributeMaxDynamicSharedMemorySize, GEMM_SMEM);
    cudaFuncSetAttribute(gemm_tc_kernel,
                         cudaFuncAttributeMaxDynamicSharedMemorySize, GEMM_SMEM);

    dim3 gqkv(4, 33, 3);   // fused QKV: z selects projection
    qkv_gemm_kernel<<<gqkv, 256, GEMM_SMEM>>>(x, Wq, bq, Wk, bk, Wv, bv, pq, pk, pv, MROWS);
    gate_kernel<<<MROWS, 128>>>(wg);
    attn_mma_kernel<<<dim3(33, HH, BB), 128, ATTN_SMEM>>>(bg);
    gemm_tc_kernel<<<dim3(4, 33), 256, GEMM_SMEM>>>(pao, Wo, bo, out, MROWS);
}

// round 9
// speedup vs baseline: 1.3430x; 1.3430x over previous
#include <cuda_runtime.h>
#include <cuda_pipeline.h>
#include <cstdint>
#include <math.h>

#define BB 2
#define SS 2049
#define EE 512
#define HH 8
#define WINW 1024
#define MROWS (BB * SS)                  // 4098
#define SCALE 0.125f                     // D^-0.5
#define BIASC (-1.9073486328125e-6f)     // -0.5/(512^2)
#define LOG2E 1.4426950408889634f

// Scratch (device globals: no allocation allowed)
__device__ float g_q[MROWS * EE];
__device__ float g_k[MROWS * EE];
__device__ float g_v[MROWS * EE];
__device__ float g_ao[MROWS * EE];
__device__ float g_gq[MROWS];
__device__ float g_gk[MROWS];

// ============================================================================
// helpers
// ============================================================================
__device__ __forceinline__ float tf32r(float x) {
    uint32_t u;
    asm("cvt.rna.tf32.f32 %0, %1;" : "=r"(u) : "f"(x));
    return __uint_as_float(u);
}
__device__ __forceinline__ void mma_tf32(float* d, const uint32_t* a, const uint32_t* b) {
    asm volatile(
        "mma.sync.aligned.m16n8k8.row.col.f32.tf32.tf32.f32 "
        "{%0,%1,%2,%3}, {%4,%5,%6,%7}, {%8,%9}, {%0,%1,%2,%3};"
        : "+f"(d[0]), "+f"(d[1]), "+f"(d[2]), "+f"(d[3])
        : "r"(a[0]), "r"(a[1]), "r"(a[2]), "r"(a[3]), "r"(b[0]), "r"(b[1]));
}
__device__ __forceinline__ float rcpf(float x) {
    float r;
    asm("rcp.approx.f32 %0, %1;" : "=f"(r) : "f"(x));
    return r;
}
__device__ __forceinline__ float ex2f(float x) {
    float r;
    asm("ex2.approx.f32 %0, %1;" : "=f"(r) : "f"(x));
    return r;
}

// ---------------------------------------------------------------------------
// 1xTF32 GEMM body (rna-rounded at staging), software-pipelined
// double-buffered. C[M,512] = A[M,512] @ B[512,512] + bias
// BM=128 BN=128 BK=16, 256 threads (8 warps: 4M x 2N), warp tile 32x64, occ 2
// ---------------------------------------------------------------------------
#define GSTR 136
#define TILEF (16 * GSTR)
#define GEMM_SMEM (4 * TILEF * 4)         // 2 bufs x (A+B) = 34816 bytes

__device__ __forceinline__ void gemm_body(
    const float* __restrict__ A, const float* __restrict__ B,
    const float* __restrict__ bias, float* __restrict__ C, int M,
    int row0, int col0, float* sm)
{
    float* Ab = sm;                  // [2][16][GSTR]  (A transposed: [k][m])
    float* Bb = sm + 2 * TILEF;      // [2][16][GSTR]  (B: [k][n])

    const int tid = threadIdx.x;
    const int wid = tid >> 5, lane = tid & 31;
    const int g = lane >> 2, tg = lane & 3;
    const int wm = wid >> 1, wn = wid & 1;
    const int wrow = wm * 32, wcol = wn * 64;

    const int a_r0 = tid >> 2, a_c = (tid & 3) * 4;
    const int b_k0 = tid >> 5, b_c = (tid & 31) * 4;

    float acc[2][8][4];
#pragma unroll
    for (int mt = 0; mt < 2; mt++)
#pragma unroll
        for (int nt = 0; nt < 8; nt++)
#pragma unroll
            for (int e = 0; e < 4; e++) acc[mt][nt][e] = 0.f;

    float4 pa[2], pb[2];

#define G_LDG(K0)                                                              \
    {                                                                          \
        _Pragma("unroll")                                                      \
        for (int it = 0; it < 2; it++) {                                       \
            int r = a_r0 + it * 64;                                            \
            pa[it] = make_float4(0.f, 0.f, 0.f, 0.f);                          \
            if (row0 + r < M)                                                  \
                pa[it] = *(const float4*)&A[(size_t)(row0 + r) * 512 + (K0) + a_c]; \
            int kr = b_k0 + it * 8;                                            \
            pb[it] = *(const float4*)&B[(size_t)((K0) + kr) * 512 + col0 + b_c];    \
        }                                                                      \
    }

#define G_STS(Q)                                                               \
    {                                                                          \
        float* ab = Ab + (Q) * TILEF;                                          \
        float* bb = Bb + (Q) * TILEF;                                          \
        _Pragma("unroll")                                                      \
        for (int it = 0; it < 2; it++) {                                       \
            int r = a_r0 + it * 64;                                            \
            ab[(a_c + 0) * GSTR + r] = tf32r(pa[it].x);                        \
            ab[(a_c + 1) * GSTR + r] = tf32r(pa[it].y);                        \
            ab[(a_c + 2) * GSTR + r] = tf32r(pa[it].z);                        \
            ab[(a_c + 3) * GSTR + r] = tf32r(pa[it].w);                        \
            int kr = b_k0 + it * 8;                                            \
            float4 hv;                                                         \
            hv.x = tf32r(pb[it].x);                                            \
            hv.y = tf32r(pb[it].y);                                            \
            hv.z = tf32r(pb[it].z);                                            \
            hv.w = tf32r(pb[it].w);                                            \
            *(float4*)&bb[kr * GSTR + b_c] = hv;                               \
        }                                                                      \
    }

    G_LDG(0);
    G_STS(0);
    G_LDG(16);
    __syncthreads();

    int p = 0;
    for (int k0 = 0; k0 < 512; k0 += 16) {
        if (k0 + 16 < 512) {
            G_STS(1 - p);
            if (k0 + 32 < 512) G_LDG(k0 + 32);
        }

        const float* ab_ = Ab + p * TILEF;
        const float* bb_ = Bb + p * TILEF;
#pragma unroll
        for (int ks = 0; ks < 2; ks++) {
            const int kk = ks * 8;
            uint32_t af[2][4];
#pragma unroll
            for (int mt = 0; mt < 2; mt++) {
                int r = wrow + mt * 16;
                af[mt][0] = __float_as_uint(ab_[(kk + tg) * GSTR + r + g]);
                af[mt][1] = __float_as_uint(ab_[(kk + tg) * GSTR + r + g + 8]);
                af[mt][2] = __float_as_uint(ab_[(kk + tg + 4) * GSTR + r + g]);
                af[mt][3] = __float_as_uint(ab_[(kk + tg + 4) * GSTR + r + g + 8]);
            }
            uint32_t bf[8][2];
#pragma unroll
            for (int nt = 0; nt < 8; nt++) {
                int c = wcol + nt * 8;
                bf[nt][0] = __float_as_uint(bb_[(kk + tg) * GSTR + c + g]);
                bf[nt][1] = __float_as_uint(bb_[(kk + tg + 4) * GSTR + c + g]);
            }
#pragma unroll
            for (int mt = 0; mt < 2; mt++)
#pragma unroll
                for (int nt = 0; nt < 8; nt++)
                    mma_tf32(acc[mt][nt], af[mt], bf[nt]);
        }

        if (k0 + 16 < 512) {
            __syncthreads();
            p ^= 1;
        }
    }

#pragma unroll
    for (int mt = 0; mt < 2; mt++) {
        int r0 = row0 + wrow + mt * 16 + g;
#pragma unroll
        for (int nt = 0; nt < 8; nt++) {
            int c = col0 + wcol + nt * 8 + 2 * tg;
            float b0v = bias[c], b1v = bias[c + 1];
            if (r0 < M) {
                float2 o = make_float2(acc[mt][nt][0] + b0v, acc[mt][nt][1] + b1v);
                *(float2*)&C[(size_t)r0 * 512 + c] = o;
            }
            if (r0 + 8 < M) {
                float2 o = make_float2(acc[mt][nt][2] + b0v, acc[mt][nt][3] + b1v);
                *(float2*)&C[(size_t)(r0 + 8) * 512 + c] = o;
            }
        }
    }
#undef G_LDG
#undef G_STS
}

__global__ __launch_bounds__(256, 2) void qkv_gemm_kernel(
    const float* __restrict__ A,
    const float* __restrict__ Wq, const float* __restrict__ bq,
    const float* __restrict__ Wk, const float* __restrict__ bk,
    const float* __restrict__ Wv, const float* __restrict__ bv,
    float* __restrict__ Cq, float* __restrict__ Ck, float* __restrict__ Cv,
    int M)
{
    extern __shared__ float gsm[];
    const float* B;
    const float* bias;
    float* C;
    if (blockIdx.z == 0)      { B = Wq; bias = bq; C = Cq; }
    else if (blockIdx.z == 1) { B = Wk; bias = bk; C = Ck; }
    else                      { B = Wv; bias = bv; C = Cv; }
    gemm_body(A, B, bias, C, M, blockIdx.y * 128, blockIdx.x * 128, gsm);
}

__global__ __launch_bounds__(256, 2) void gemm_tc_kernel(
    const float* __restrict__ A, const float* __restrict__ B,
    const float* __restrict__ bias, float* __restrict__ C, int M)
{
    extern __shared__ float gsm[];
    gemm_body(A, B, bias, C, M, blockIdx.y * 128, blockIdx.x * 128, gsm);
}

// ---------------------------------------------------------------------------
// Gate dot products
// ---------------------------------------------------------------------------
__global__ __launch_bounds__(128) void gate_kernel(const float* __restrict__ wg)
{
    const int row = blockIdx.x;
    const int tid = threadIdx.x;
    float sq = 0.f, sk = 0.f;
#pragma unroll
    for (int e = tid; e < 512; e += 128) {
        sq += g_q[(size_t)row * 512 + e] * wg[e];
        sk += g_k[(size_t)row * 512 + e] * wg[512 + e];
    }
#pragma unroll
    for (int off = 16; off >= 1; off >>= 1) {
        sq += __shfl_down_sync(0xffffffffu, sq, off);
        sk += __shfl_down_sync(0xffffffffu, sk, off);
    }
    __shared__ float pq[4], pk[4];
    if ((tid & 31) == 0) { pq[tid >> 5] = sq; pk[tid >> 5] = sk; }
    __syncthreads();
    if (tid == 0) {
        g_gq[row] = pq[0] + pq[1] + pq[2] + pq[3];
        g_gk[row] = pk[0] + pk[1] + pk[2] + pk[3];
    }
}

// ---------------------------------------------------------------------------
// TF32 mma.sync flash attention with cp.async double-buffered K/V staging.
// (unchanged from R7)
// ---------------------------------------------------------------------------
#define ASTR 68
#define TILE68 (64 * ASTR)
#define ATTN_SMEM ((6 * TILE68 + 128 + 32) * 4)

__global__ __launch_bounds__(128, 2) void attn_mma_kernel(const float* __restrict__ bg_ptr)
{
    extern __shared__ float sm[];
    float* Qs   = sm;                       // [64][ASTR]
    float* Ps   = sm + 5 * TILE68;          // [64][ASTR]
    float* egk  = sm + 6 * TILE68;          // [2][64]

    const int qb = blockIdx.x, h = blockIdx.y, b = blockIdx.z;
    const int q0 = qb * 64;
    const int tid = threadIdx.x;
    const int lane = tid & 31;
    const int g = lane >> 2, tg = lane & 3;
    const int wrow = (tid >> 5) * 16;
    const float bg = bg_ptr[0];

    const float* qp = g_q + ((size_t)(b * SS)) * EE + h * 64;
    const float* kp = g_k + ((size_t)(b * SS)) * EE + h * 64;
    const float* vp = g_v + ((size_t)(b * SS)) * EE + h * 64;

    int kstart = q0 - WINW; if (kstart < 0) kstart = 0;
    int kend = q0 + 64 + WINW; if (kend > SS) kend = SS;

    const int s_r = tid >> 4, s_c = (tid & 15) * 4;
#define STAGE_KV(K0, BBUF)                                                     \
    {                                                                          \
        float* Kb = sm + (1 + (BBUF)) * TILE68;                                \
        float* Vb = sm + (3 + (BBUF)) * TILE68;                                \
        _Pragma("unroll")                                                      \
        for (int it = 0; it < 8; it++) {                                       \
            int r = s_r + it * 8;                                              \
            int gj = (K0) + r;                                                 \
            size_t off = (size_t)gj * EE + s_c;                                \
            int zf = (gj < SS) ? 0 : 16;                                       \
            __pipeline_memcpy_async(&Kb[r * ASTR + s_c], kp + off, 16, zf);    \
            __pipeline_memcpy_async(&Vb[r * ASTR + s_c], vp + off, 16, zf);    \
        }                                                                      \
        __pipeline_commit();                                                   \
    }

    STAGE_KV(kstart, 0);
    float gk_reg = 0.f;
    if (tid < 64) {
        int gj = kstart + tid;
        gk_reg = (gj < SS) ? g_gk[b * SS + gj] : 0.f;
    }

#pragma unroll
    for (int it = 0; it < 8; it++) {
        int idx = it * 128 + tid;
        int r = idx >> 4, c4 = (idx & 15) * 4;
        int gi = q0 + r;
        float4 v = make_float4(0.f, 0.f, 0.f, 0.f);
        if (gi < SS) v = *(const float4*)(qp + (size_t)gi * EE + c4);
        Qs[r * ASTR + c4 + 0] = tf32r(v.x);
        Qs[r * ASTR + c4 + 1] = tf32r(v.y);
        Qs[r * ASTR + c4 + 2] = tf32r(v.z);
        Qs[r * ASTR + c4 + 3] = tf32r(v.w);
    }
    __syncthreads();

    uint32_t qa[8][4];
#pragma unroll
    for (int kk = 0; kk < 8; kk++) {
        qa[kk][0] = __float_as_uint(Qs[(wrow + g) * ASTR + kk * 8 + tg]);
        qa[kk][1] = __float_as_uint(Qs[(wrow + g + 8) * ASTR + kk * 8 + tg]);
        qa[kk][2] = __float_as_uint(Qs[(wrow + g) * ASTR + kk * 8 + tg + 4]);
        qa[kk][3] = __float_as_uint(Qs[(wrow + g + 8) * ASTR + kk * 8 + tg + 4]);
    }
    const int gi0 = q0 + wrow + g, gi1 = gi0 + 8;
    const float egq0 = __expf(-((gi0 < SS) ? g_gq[b * SS + gi0] : 0.f));
    const float egq1 = __expf(-((gi1 < SS) ? g_gq[b * SS + gi1] : 0.f));

    float oacc[8][4];
#pragma unroll
    for (int nt = 0; nt < 8; nt++)
#pragma unroll
        for (int e = 0; e < 4; e++) oacc[nt][e] = 0.f;
    float l0 = 0.f, l1 = 0.f;

    const float C1 = SCALE * LOG2E;
    const float C2 = BIASC * LOG2E;

    int p = 0;
    for (int k0 = kstart; k0 < kend; k0 += 64, p ^= 1) {
        __pipeline_wait_prior(0);
        __syncthreads();

        if (tid < 64) egk[p * 64 + tid] = __expf(-gk_reg - bg);
        if (k0 + 64 < kend) {
            STAGE_KV(k0 + 64, 1 - p);
            if (tid < 64) {
                int gj = k0 + 64 + tid;
                gk_reg = (gj < SS) ? g_gk[b * SS + gj] : 0.f;
            }
        }
        __syncthreads();

        const float* Kb = sm + (1 + p) * TILE68;
        const float* Vb = sm + (3 + p) * TILE68;
        const float* eg_s = egk + p * 64;

        float sacc[8][4];
#pragma unroll
        for (int nt = 0; nt < 8; nt++)
#pragma unroll
            for (int e = 0; e < 4; e++) sacc[nt][e] = 0.f;
#pragma unroll
        for (int kk = 0; kk < 8; kk++) {
#pragma unroll
            for (int nt = 0; nt < 8; nt++) {
                uint32_t bf[2];
                bf[0] = __float_as_uint(Kb[(nt * 8 + g) * ASTR + kk * 8 + tg]);
                bf[1] = __float_as_uint(Kb[(nt * 8 + g) * ASTR + kk * 8 + tg + 4]);
                mma_tf32(sacc[nt], qa[kk], bf);
            }
        }

        float lt0 = 0.f, lt1 = 0.f;
#pragma unroll
        for (int nt = 0; nt < 8; nt++) {
            int lj = nt * 8 + 2 * tg;
            float2 eg = *(float2*)&eg_s[lj];
            int gj0 = k0 + lj, gj1 = gj0 + 1;

            int d00 = gi0 - gj0, d01 = gi0 - gj1, d10 = gi1 - gj0, d11 = gi1 - gj1;
            float p00, p01, p10, p11;
            {
                float gate = rcpf(fmaf(egq0, eg.x, 1.f));
                float pe = ex2f((sacc[nt][0] * C1 + (float)(d00 * d00) * C2) * gate);
                p00 = (gj0 < SS && d00 <= WINW && d00 >= -WINW) ? tf32r(pe) : 0.f;
            }
            {
                float gate = rcpf(fmaf(egq0, eg.y, 1.f));
                float pe = ex2f((sacc[nt][1] * C1 + (float)(d01 * d01) * C2) * gate);
                p01 = (gj1 < SS && d01 <= WINW && d01 >= -WINW) ? tf32r(pe) : 0.f;
            }
            {
                float gate = rcpf(fmaf(egq1, eg.x, 1.f));
                float pe = ex2f((sacc[nt][2] * C1 + (float)(d10 * d10) * C2) * gate);
                p10 = (gj0 < SS && d10 <= WINW && d10 >= -WINW) ? tf32r(pe) : 0.f;
            }
            {
                float gate = rcpf(fmaf(egq1, eg.y, 1.f));
                float pe = ex2f((sacc[nt][3] * C1 + (float)(d11 * d11) * C2) * gate);
                p11 = (gj1 < SS && d11 <= WINW && d11 >= -WINW) ? tf32r(pe) : 0.f;
            }
            lt0 += p00 + p01;
            lt1 += p10 + p11;
            *(float2*)&Ps[(wrow + g) * ASTR + lj] = make_float2(p00, p01);
            *(float2*)&Ps[(wrow + g + 8) * ASTR + lj] = make_float2(p10, p11);
        }
        lt0 += __shfl_xor_sync(0xffffffffu, lt0, 1);
        lt0 += __shfl_xor_sync(0xffffffffu, lt0, 2);
        lt1 += __shfl_xor_sync(0xffffffffu, lt1, 1);
        lt1 += __shfl_xor_sync(0xffffffffu, lt1, 2);
        l0 += lt0;
        l1 += lt1;
        __syncwarp();

#pragma unroll
        for (int kk = 0; kk < 8; kk++) {
            uint32_t pa[4];
            pa[0] = __float_as_uint(Ps[(wrow + g) * ASTR + kk * 8 + tg]);
            pa[1] = __float_as_uint(Ps[(wrow + g + 8) * ASTR + kk * 8 + tg]);
            pa[2] = __float_as_uint(Ps[(wrow + g) * ASTR + kk * 8 + tg + 4]);
            pa[3] = __float_as_uint(Ps[(wrow + g + 8) * ASTR + kk * 8 + tg + 4]);
#pragma unroll
            for (int nt = 0; nt < 8; nt++) {
                uint32_t bf[2];
                bf[0] = __float_as_uint(Vb[(kk * 8 + tg) * ASTR + nt * 8 + g]);
                bf[1] = __float_as_uint(Vb[(kk * 8 + tg + 4) * ASTR + nt * 8 + g]);
                mma_tf32(oacc[nt], pa, bf);
            }
        }
    }

    const float inv0 = rcpf(l0), inv1 = rcpf(l1);
    float* op = g_ao + ((size_t)(b * SS)) * EE + h * 64;
#pragma unroll
    for (int nt = 0; nt < 8; nt++) {
        int c = nt * 8 + 2 * tg;
        if (gi0 < SS)
            *(float2*)&op[(size_t)gi0 * EE + c] =
                make_float2(oacc[nt][0] * inv0, oacc[nt][1] * inv0);
        if (gi1 < SS)
            *(float2*)&op[(size_t)gi1 * EE + c] =
                make_float2(oacc[nt][2] * inv1, oacc[nt][3] * inv1);
    }
#undef STAGE_KV
}

// ---------------------------------------------------------------------------
extern "C" void kernel_launch(void* const* d_in, const int* in_sizes, int n_in,
                              void* d_out, int out_size)
{
    const float* x  = (const float*)d_in[0];
    const float* Wq = (const float*)d_in[1];
    const float* bq = (const float*)d_in[2];
    const float* Wk = (const float*)d_in[3];
    const float* bk = (const float*)d_in[4];
    const float* Wv = (const float*)d_in[5];
    const float* bv = (const float*)d_in[6];
    const float* Wo = (const float*)d_in[7];
    const float* bo = (const float*)d_in[8];
    const float* wg = (const float*)d_in[9];
    const float* bg = (const float*)d_in[10];
    float* out = (float*)d_out;

    float *pq, *pk, *pv, *pao;
    cudaGetSymbolAddress((void**)&pq, g_q);
    cudaGetSymbolAddress((void**)&pk, g_k);
    cudaGetSymbolAddress((void**)&pv, g_v);
    cudaGetSymbolAddress((void**)&pao, g_ao);

    cudaFuncSetAttribute(attn_mma_kernel,
                         cudaFuncAttributeMaxDynamicSharedMemorySize, ATTN_SMEM);
    cudaFuncSetAttribute(qkv_gemm_kernel,
                         cudaFuncAttributeMaxDynamicSharedMemorySize, GEMM_SMEM);
    cudaFuncSetAttribute(gemm_tc_kernel,
                         cudaFuncAttributeMaxDynamicSharedMemorySize, GEMM_SMEM);

    dim3 gqkv(4, 33, 3);   // fused QKV: z selects projection
    qkv_gemm_kernel<<<gqkv, 256, GEMM_SMEM>>>(x, Wq, bq, Wk, bk, Wv, bv, pq, pk, pv, MROWS);
    gate_kernel<<<MROWS, 128>>>(wg);
    attn_mma_kernel<<<dim3(33, HH, BB), 128, ATTN_SMEM>>>(bg);
    gemm_tc_kernel<<<dim3(4, 33), 256, GEMM_SMEM>>>(pao, Wo, bo, out, MROWS);
}

// round 10
// speedup vs baseline: 1.6012x; 1.1922x over previous
#include <cuda_runtime.h>
#include <cuda_pipeline.h>
#include <cstdint>
#include <math.h>

#define BB 2
#define SS 2049
#define EE 512
#define HH 8
#define WINW 1024
#define MROWS (BB * SS)                  // 4098
#define SCALE 0.125f                     // D^-0.5
#define BIASC (-1.9073486328125e-6f)     // -0.5/(512^2)
#define LOG2E 1.4426950408889634f

// Scratch (device globals: no allocation allowed)
__device__ float g_q[MROWS * EE];
__device__ float g_k[MROWS * EE];
__device__ float g_v[MROWS * EE];
__device__ float g_ao[MROWS * EE];
__device__ float g_gq[MROWS];
__device__ float g_gk[MROWS];

// ============================================================================
// helpers
// ============================================================================
__device__ __forceinline__ float tf32r(float x) {
    uint32_t u;
    asm("cvt.rna.tf32.f32 %0, %1;" : "=r"(u) : "f"(x));
    return __uint_as_float(u);
}
__device__ __forceinline__ void mma_tf32(float* d, const uint32_t* a, const uint32_t* b) {
    asm volatile(
        "mma.sync.aligned.m16n8k8.row.col.f32.tf32.tf32.f32 "
        "{%0,%1,%2,%3}, {%4,%5,%6,%7}, {%8,%9}, {%0,%1,%2,%3};"
        : "+f"(d[0]), "+f"(d[1]), "+f"(d[2]), "+f"(d[3])
        : "r"(a[0]), "r"(a[1]), "r"(a[2]), "r"(a[3]), "r"(b[0]), "r"(b[1]));
}
__device__ __forceinline__ float rcpf(float x) {
    float r;
    asm("rcp.approx.f32 %0, %1;" : "=f"(r) : "f"(x));
    return r;
}
__device__ __forceinline__ float ex2f(float x) {
    float r;
    asm("ex2.approx.f32 %0, %1;" : "=f"(r) : "f"(x));
    return r;
}

// ---------------------------------------------------------------------------
// 1xTF32 GEMM body (rna-rounded at staging), software-pipelined
// double-buffered. (unchanged from R9)
// ---------------------------------------------------------------------------
#define GSTR 136
#define TILEF (16 * GSTR)
#define GEMM_SMEM (4 * TILEF * 4)

__device__ __forceinline__ void gemm_body(
    const float* __restrict__ A, const float* __restrict__ B,
    const float* __restrict__ bias, float* __restrict__ C, int M,
    int row0, int col0, float* sm)
{
    float* Ab = sm;
    float* Bb = sm + 2 * TILEF;

    const int tid = threadIdx.x;
    const int wid = tid >> 5, lane = tid & 31;
    const int g = lane >> 2, tg = lane & 3;
    const int wm = wid >> 1, wn = wid & 1;
    const int wrow = wm * 32, wcol = wn * 64;

    const int a_r0 = tid >> 2, a_c = (tid & 3) * 4;
    const int b_k0 = tid >> 5, b_c = (tid & 31) * 4;

    float acc[2][8][4];
#pragma unroll
    for (int mt = 0; mt < 2; mt++)
#pragma unroll
        for (int nt = 0; nt < 8; nt++)
#pragma unroll
            for (int e = 0; e < 4; e++) acc[mt][nt][e] = 0.f;

    float4 pa[2], pb[2];

#define G_LDG(K0)                                                              \
    {                                                                          \
        _Pragma("unroll")                                                      \
        for (int it = 0; it < 2; it++) {                                       \
            int r = a_r0 + it * 64;                                            \
            pa[it] = make_float4(0.f, 0.f, 0.f, 0.f);                          \
            if (row0 + r < M)                                                  \
                pa[it] = *(const float4*)&A[(size_t)(row0 + r) * 512 + (K0) + a_c]; \
            int kr = b_k0 + it * 8;                                            \
            pb[it] = *(const float4*)&B[(size_t)((K0) + kr) * 512 + col0 + b_c];    \
        }                                                                      \
    }

#define G_STS(Q)                                                               \
    {                                                                          \
        float* ab = Ab + (Q) * TILEF;                                          \
        float* bb = Bb + (Q) * TILEF;                                          \
        _Pragma("unroll")                                                      \
        for (int it = 0; it < 2; it++) {                                       \
            int r = a_r0 + it * 64;                                            \
            ab[(a_c + 0) * GSTR + r] = tf32r(pa[it].x);                        \
            ab[(a_c + 1) * GSTR + r] = tf32r(pa[it].y);                        \
            ab[(a_c + 2) * GSTR + r] = tf32r(pa[it].z);                        \
            ab[(a_c + 3) * GSTR + r] = tf32r(pa[it].w);                        \
            int kr = b_k0 + it * 8;                                            \
            float4 hv;                                                         \
            hv.x = tf32r(pb[it].x);                                            \
            hv.y = tf32r(pb[it].y);                                            \
            hv.z = tf32r(pb[it].z);                                            \
            hv.w = tf32r(pb[it].w);                                            \
            *(float4*)&bb[kr * GSTR + b_c] = hv;                               \
        }                                                                      \
    }

    G_LDG(0);
    G_STS(0);
    G_LDG(16);
    __syncthreads();

    int p = 0;
    for (int k0 = 0; k0 < 512; k0 += 16) {
        if (k0 + 16 < 512) {
            G_STS(1 - p);
            if (k0 + 32 < 512) G_LDG(k0 + 32);
        }

        const float* ab_ = Ab + p * TILEF;
        const float* bb_ = Bb + p * TILEF;
#pragma unroll
        for (int ks = 0; ks < 2; ks++) {
            const int kk = ks * 8;
            uint32_t af[2][4];
#pragma unroll
            for (int mt = 0; mt < 2; mt++) {
                int r = wrow + mt * 16;
                af[mt][0] = __float_as_uint(ab_[(kk + tg) * GSTR + r + g]);
                af[mt][1] = __float_as_uint(ab_[(kk + tg) * GSTR + r + g + 8]);
                af[mt][2] = __float_as_uint(ab_[(kk + tg + 4) * GSTR + r + g]);
                af[mt][3] = __float_as_uint(ab_[(kk + tg + 4) * GSTR + r + g + 8]);
            }
            uint32_t bf[8][2];
#pragma unroll
            for (int nt = 0; nt < 8; nt++) {
                int c = wcol + nt * 8;
                bf[nt][0] = __float_as_uint(bb_[(kk + tg) * GSTR + c + g]);
                bf[nt][1] = __float_as_uint(bb_[(kk + tg + 4) * GSTR + c + g]);
            }
#pragma unroll
            for (int mt = 0; mt < 2; mt++)
#pragma unroll
                for (int nt = 0; nt < 8; nt++)
                    mma_tf32(acc[mt][nt], af[mt], bf[nt]);
        }

        if (k0 + 16 < 512) {
            __syncthreads();
            p ^= 1;
        }
    }

#pragma unroll
    for (int mt = 0; mt < 2; mt++) {
        int r0 = row0 + wrow + mt * 16 + g;
#pragma unroll
        for (int nt = 0; nt < 8; nt++) {
            int c = col0 + wcol + nt * 8 + 2 * tg;
            float b0v = bias[c], b1v = bias[c + 1];
            if (r0 < M) {
                float2 o = make_float2(acc[mt][nt][0] + b0v, acc[mt][nt][1] + b1v);
                *(float2*)&C[(size_t)r0 * 512 + c] = o;
            }
            if (r0 + 8 < M) {
                float2 o = make_float2(acc[mt][nt][2] + b0v, acc[mt][nt][3] + b1v);
                *(float2*)&C[(size_t)(r0 + 8) * 512 + c] = o;
            }
        }
    }
#undef G_LDG
#undef G_STS
}

__global__ __launch_bounds__(256, 2) void qkv_gemm_kernel(
    const float* __restrict__ A,
    const float* __restrict__ Wq, const float* __restrict__ bq,
    const float* __restrict__ Wk, const float* __restrict__ bk,
    const float* __restrict__ Wv, const float* __restrict__ bv,
    float* __restrict__ Cq, float* __restrict__ Ck, float* __restrict__ Cv,
    int M)
{
    extern __shared__ float gsm[];
    const float* B;
    const float* bias;
    float* C;
    if (blockIdx.z == 0)      { B = Wq; bias = bq; C = Cq; }
    else if (blockIdx.z == 1) { B = Wk; bias = bk; C = Ck; }
    else                      { B = Wv; bias = bv; C = Cv; }
    gemm_body(A, B, bias, C, M, blockIdx.y * 128, blockIdx.x * 128, gsm);
}

__global__ __launch_bounds__(256, 2) void gemm_tc_kernel(
    const float* __restrict__ A, const float* __restrict__ B,
    const float* __restrict__ bias, float* __restrict__ C, int M)
{
    extern __shared__ float gsm[];
    gemm_body(A, B, bias, C, M, blockIdx.y * 128, blockIdx.x * 128, gsm);
}

// ---------------------------------------------------------------------------
// Gate dot products
// ---------------------------------------------------------------------------
__global__ __launch_bounds__(128) void gate_kernel(const float* __restrict__ wg)
{
    const int row = blockIdx.x;
    const int tid = threadIdx.x;
    float sq = 0.f, sk = 0.f;
#pragma unroll
    for (int e = tid; e < 512; e += 128) {
        sq += g_q[(size_t)row * 512 + e] * wg[e];
        sk += g_k[(size_t)row * 512 + e] * wg[512 + e];
    }
#pragma unroll
    for (int off = 16; off >= 1; off >>= 1) {
        sq += __shfl_down_sync(0xffffffffu, sq, off);
        sk += __shfl_down_sync(0xffffffffu, sk, off);
    }
    __shared__ float pq[4], pk[4];
    if ((tid & 31) == 0) { pq[tid >> 5] = sq; pk[tid >> 5] = sk; }
    __syncthreads();
    if (tid == 0) {
        g_gq[row] = pq[0] + pq[1] + pq[2] + pq[3];
        g_gk[row] = pk[0] + pk[1] + pk[2] + pk[3];
    }
}

// ---------------------------------------------------------------------------
// TF32 mma.sync flash attention, cp.async double-buffered K/V staging.
// R10: P stays in registers (V rows permuted at staging so accumulator
// layout == A-fragment layout); one __syncthreads per tile (egk written
// one tile ahead into its double buffer).
// ---------------------------------------------------------------------------
#define ASTR 68
#define TILE68 (64 * ASTR)
// Qs + Kb[2] + Vb[2] + egk[2][64]
#define ATTN_SMEM ((5 * TILE68 + 128 + 16) * 4)

__global__ __launch_bounds__(128, 2) void attn_mma_kernel(const float* __restrict__ bg_ptr)
{
    extern __shared__ float sm[];
    float* Qs   = sm;                       // [64][ASTR]
    float* egk  = sm + 5 * TILE68;          // [2][64]

    const int qb = blockIdx.x, h = blockIdx.y, b = blockIdx.z;
    const int q0 = qb * 64;
    const int tid = threadIdx.x;
    const int lane = tid & 31;
    const int g = lane >> 2, tg = lane & 3;
    const int wrow = (tid >> 5) * 16;
    const float bg = bg_ptr[0];

    const float* qp = g_q + ((size_t)(b * SS)) * EE + h * 64;
    const float* kp = g_k + ((size_t)(b * SS)) * EE + h * 64;
    const float* vp = g_v + ((size_t)(b * SS)) * EE + h * 64;

    int kstart = q0 - WINW; if (kstart < 0) kstart = 0;
    int kend = q0 + 64 + WINW; if (kend > SS) kend = SS;

    const int s_r = tid >> 4, s_c = (tid & 15) * 4;
    // permuted V destination row within 8-block: 2t->t, 2t+1->t+4
    const int s_rp = (s_r & 1) ? ((s_r >> 1) + 4) : (s_r >> 1);
#define STAGE_KV(K0, BBUF)                                                     \
    {                                                                          \
        float* Kb = sm + (1 + (BBUF)) * TILE68;                                \
        float* Vb = sm + (3 + (BBUF)) * TILE68;                                \
        _Pragma("unroll")                                                      \
        for (int it = 0; it < 8; it++) {                                       \
            int r = s_r + it * 8;                                              \
            int gj = (K0) + r;                                                 \
            size_t off = (size_t)gj * EE + s_c;                                \
            int zf = (gj < SS) ? 0 : 16;                                       \
            __pipeline_memcpy_async(&Kb[r * ASTR + s_c], kp + off, 16, zf);    \
            __pipeline_memcpy_async(&Vb[(it * 8 + s_rp) * ASTR + s_c],         \
                                    vp + off, 16, zf);                         \
        }                                                                      \
        __pipeline_commit();                                                   \
    }

    // prologue: stage tile 0, write egk[0], prefetch gk for tile 1
    STAGE_KV(kstart, 0);
    float gk_reg = 0.f;
    if (tid < 64) {
        int gj = kstart + tid;
        gk_reg = (gj < SS) ? g_gk[b * SS + gj] : 0.f;
    }

#pragma unroll
    for (int it = 0; it < 8; it++) {
        int idx = it * 128 + tid;
        int r = idx >> 4, c4 = (idx & 15) * 4;
        int gi = q0 + r;
        float4 v = make_float4(0.f, 0.f, 0.f, 0.f);
        if (gi < SS) v = *(const float4*)(qp + (size_t)gi * EE + c4);
        Qs[r * ASTR + c4 + 0] = tf32r(v.x);
        Qs[r * ASTR + c4 + 1] = tf32r(v.y);
        Qs[r * ASTR + c4 + 2] = tf32r(v.z);
        Qs[r * ASTR + c4 + 3] = tf32r(v.w);
    }
    if (tid < 64) {
        egk[tid] = __expf(-gk_reg - bg);          // tile 0 -> buffer 0
        if (kstart + 64 < kend) {
            int gj = kstart + 64 + tid;
            gk_reg = (gj < SS) ? g_gk[b * SS + gj] : 0.f;
        }
    }
    __syncthreads();

    uint32_t qa[8][4];
#pragma unroll
    for (int kk = 0; kk < 8; kk++) {
        qa[kk][0] = __float_as_uint(Qs[(wrow + g) * ASTR + kk * 8 + tg]);
        qa[kk][1] = __float_as_uint(Qs[(wrow + g + 8) * ASTR + kk * 8 + tg]);
        qa[kk][2] = __float_as_uint(Qs[(wrow + g) * ASTR + kk * 8 + tg + 4]);
        qa[kk][3] = __float_as_uint(Qs[(wrow + g + 8) * ASTR + kk * 8 + tg + 4]);
    }
    const int gi0 = q0 + wrow + g, gi1 = gi0 + 8;
    const float egq0 = __expf(-((gi0 < SS) ? g_gq[b * SS + gi0] : 0.f));
    const float egq1 = __expf(-((gi1 < SS) ? g_gq[b * SS + gi1] : 0.f));

    float oacc[8][4];
#pragma unroll
    for (int nt = 0; nt < 8; nt++)
#pragma unroll
        for (int e = 0; e < 4; e++) oacc[nt][e] = 0.f;
    float l0 = 0.f, l1 = 0.f;

    const float C1 = SCALE * LOG2E;
    const float C2 = BIASC * LOG2E;

    int p = 0;
    for (int k0 = kstart; k0 < kend; k0 += 64, p ^= 1) {
        __pipeline_wait_prior(0);      // this tile's K/V landed
        __syncthreads();               // all done with buffer 1-p; egk[p] visible

        // stage NEXT tile (buffer 1-p) + its egk; prefetch gk after that
        if (k0 + 64 < kend) {
            STAGE_KV(k0 + 64, 1 - p);
            if (tid < 64) {
                egk[(1 - p) * 64 + tid] = __expf(-gk_reg - bg);
                if (k0 + 128 < kend) {
                    int gj = k0 + 128 + tid;
                    gk_reg = (gj < SS) ? g_gk[b * SS + gj] : 0.f;
                }
            }
        }

        const float* Kb = sm + (1 + p) * TILE68;
        const float* Vb = sm + (3 + p) * TILE68;
        const float* eg_s = egk + p * 64;

        // ---- S = Q @ K^T ----
        float sacc[8][4];
#pragma unroll
        for (int nt = 0; nt < 8; nt++)
#pragma unroll
            for (int e = 0; e < 4; e++) sacc[nt][e] = 0.f;
#pragma unroll
        for (int kk = 0; kk < 8; kk++) {
#pragma unroll
            for (int nt = 0; nt < 8; nt++) {
                uint32_t bf[2];
                bf[0] = __float_as_uint(Kb[(nt * 8 + g) * ASTR + kk * 8 + tg]);
                bf[1] = __float_as_uint(Kb[(nt * 8 + g) * ASTR + kk * 8 + tg + 4]);
                mma_tf32(sacc[nt], qa[kk], bf);
            }
        }

        // ---- Epilogue: gate + bias + mask + exp; P stays in sacc regs ----
        float lt0 = 0.f, lt1 = 0.f;
#pragma unroll
        for (int nt = 0; nt < 8; nt++) {
            int lj = nt * 8 + 2 * tg;
            float2 eg = *(float2*)&eg_s[lj];
            int gj0 = k0 + lj, gj1 = gj0 + 1;

            int d00 = gi0 - gj0, d01 = gi0 - gj1, d10 = gi1 - gj0, d11 = gi1 - gj1;
            {
                float gate = rcpf(fmaf(egq0, eg.x, 1.f));
                float pe = ex2f((sacc[nt][0] * C1 + (float)(d00 * d00) * C2) * gate);
                sacc[nt][0] = (gj0 < SS && d00 <= WINW && d00 >= -WINW) ? tf32r(pe) : 0.f;
            }
            {
                float gate = rcpf(fmaf(egq0, eg.y, 1.f));
                float pe = ex2f((sacc[nt][1] * C1 + (float)(d01 * d01) * C2) * gate);
                sacc[nt][1] = (gj1 < SS && d01 <= WINW && d01 >= -WINW) ? tf32r(pe) : 0.f;
            }
            {
                float gate = rcpf(fmaf(egq1, eg.x, 1.f));
                float pe = ex2f((sacc[nt][2] * C1 + (float)(d10 * d10) * C2) * gate);
                sacc[nt][2] = (gj0 < SS && d10 <= WINW && d10 >= -WINW) ? tf32r(pe) : 0.f;
            }
            {
                float gate = rcpf(fmaf(egq1, eg.y, 1.f));
                float pe = ex2f((sacc[nt][3] * C1 + (float)(d11 * d11) * C2) * gate);
                sacc[nt][3] = (gj1 < SS && d11 <= WINW && d11 >= -WINW) ? tf32r(pe) : 0.f;
            }
            lt0 += sacc[nt][0] + sacc[nt][1];
            lt1 += sacc[nt][2] + sacc[nt][3];
        }
        lt0 += __shfl_xor_sync(0xffffffffu, lt0, 1);
        lt0 += __shfl_xor_sync(0xffffffffu, lt0, 2);
        lt1 += __shfl_xor_sync(0xffffffffu, lt1, 1);
        lt1 += __shfl_xor_sync(0xffffffffu, lt1, 2);
        l0 += lt0;
        l1 += lt1;

        // ---- O += P @ V (P direct from registers; V rows permuted) ----
#pragma unroll
        for (int kk = 0; kk < 8; kk++) {
            uint32_t pa[4];
            pa[0] = __float_as_uint(sacc[kk][0]);
            pa[1] = __float_as_uint(sacc[kk][2]);
            pa[2] = __float_as_uint(sacc[kk][1]);
            pa[3] = __float_as_uint(sacc[kk][3]);
#pragma unroll
            for (int nt = 0; nt < 8; nt++) {
                uint32_t bf[2];
                bf[0] = __float_as_uint(Vb[(kk * 8 + tg) * ASTR + nt * 8 + g]);
                bf[1] = __float_as_uint(Vb[(kk * 8 + tg + 4) * ASTR + nt * 8 + g]);
                mma_tf32(oacc[nt], pa, bf);
            }
        }
    }

    const float inv0 = rcpf(l0), inv1 = rcpf(l1);
    float* op = g_ao + ((size_t)(b * SS)) * EE + h * 64;
#pragma unroll
    for (int nt = 0; nt < 8; nt++) {
        int c = nt * 8 + 2 * tg;
        if (gi0 < SS)
            *(float2*)&op[(size_t)gi0 * EE + c] =
                make_float2(oacc[nt][0] * inv0, oacc[nt][1] * inv0);
        if (gi1 < SS)
            *(float2*)&op[(size_t)gi1 * EE + c] =
                make_float2(oacc[nt][2] * inv1, oacc[nt][3] * inv1);
    }
#undef STAGE_KV
}

// ---------------------------------------------------------------------------
extern "C" void kernel_launch(void* const* d_in, const int* in_sizes, int n_in,
                              void* d_out, int out_size)
{
    const float* x  = (const float*)d_in[0];
    const float* Wq = (const float*)d_in[1];
    const float* bq = (const float*)d_in[2];
    const float* Wk = (const float*)d_in[3];
    const float* bk = (const float*)d_in[4];
    const float* Wv = (const float*)d_in[5];
    const float* bv = (const float*)d_in[6];
    const float* Wo = (const float*)d_in[7];
    const float* bo = (const float*)d_in[8];
    const float* wg = (const float*)d_in[9];
    const float* bg = (const float*)d_in[10];
    float* out = (float*)d_out;

    float *pq, *pk, *pv, *pao;
    cudaGetSymbolAddress((void**)&pq, g_q);
    cudaGetSymbolAddress((void**)&pk, g_k);
    cudaGetSymbolAddress((void**)&pv, g_v);
    cudaGetSymbolAddress((void**)&pao, g_ao);

    cudaFuncSetAttribute(attn_mma_kernel,
                         cudaFuncAttributeMaxDynamicSharedMemorySize, ATTN_SMEM);
    cudaFuncSetAttribute(qkv_gemm_kernel,
                         cudaFuncAttributeMaxDynamicSharedMemorySize, GEMM_SMEM);
    cudaFuncSetAttribute(gemm_tc_kernel,
                         cudaFuncAttributeMaxDynamicSharedMemorySize, GEMM_SMEM);

    dim3 gqkv(4, 33, 3);   // fused QKV: z selects projection
    qkv_gemm_kernel<<<gqkv, 256, GEMM_SMEM>>>(x, Wq, bq, Wk, bk, Wv, bv, pq, pk, pv, MROWS);
    gate_kernel<<<MROWS, 128>>>(wg);
    attn_mma_kernel<<<dim3(33, HH, BB), 128, ATTN_SMEM>>>(bg);
    gemm_tc_kernel<<<dim3(4, 33), 256, GEMM_SMEM>>>(pao, Wo, bo, out, MROWS);
}